// round 1
// baseline (speedup 1.0000x reference)
#include <cuda_runtime.h>
#include <cuda_bf16.h>

// Masked attention, B=2 H=12 S=2048 D=64, fp32.
// Flash-attention SIMT baseline:
//   grid (S/64, H, B), 256 threads as 16x16, 4x4 register microtiles.
//   Qs/Ks stored d-major (transposed) with pitch 68 for conflict-light LDS.128.
//   P staged through smem between QK^T and PV GEMMs.
//   Online softmax; masked scores set to -1e20f (matches reference exactly,
//   including the fully-masked-row uniform-softmax case).

#define BQ 64
#define BK 64
#define DH 64
#define SPITCH 68          // floats; 272B rows -> 16B aligned, 2-way max conflicts
#define NTHREADS 256

__global__ void __launch_bounds__(NTHREADS)
attn_fp32_kernel(const float* __restrict__ Q,
                 const float* __restrict__ K,
                 const float* __restrict__ V,
                 const int*   __restrict__ mask,
                 float*       __restrict__ O,
                 int Hn, int S)
{
    extern __shared__ float sm[];
    float* Qs = sm;                     // [DH][SPITCH]  Qs[d*SPITCH + q]
    float* Ks = Qs + DH * SPITCH;       // [DH][SPITCH]  Ks[d*SPITCH + k]
    float* Vs = Ks + DH * SPITCH;       // [BK][SPITCH]  Vs[k*SPITCH + d]
    float* Ps = Vs + BK * SPITCH;       // [BQ][SPITCH]  Ps[q*SPITCH + k]

    const int tid = threadIdx.x;
    const int tx  = tid & 15;           // k / d microtile column group
    const int ty  = tid >> 4;           // q microtile row group

    const int b  = blockIdx.z;
    const int h  = blockIdx.y;
    const int q0 = blockIdx.x * BQ;

    const float* Qb = Q + (((size_t)b * Hn + h) * S + q0) * DH;
    const float* Kb = K + (((size_t)b * Hn + h) * S) * DH;
    const float* Vb = V + (((size_t)b * Hn + h) * S) * DH;
    const int*   Mb = mask + (size_t)b * S * S + (size_t)q0 * S;

    // ---- load Q tile, transposed into smem (d-major) ----
#pragma unroll
    for (int r = 0; r < 4; r++) {
        int v  = tid + r * NTHREADS;        // 0..1023 float4 slots
        int q  = v >> 4;
        int d0 = (v & 15) << 2;
        float4 t = *reinterpret_cast<const float4*>(Qb + (size_t)q * DH + d0);
        Qs[(d0 + 0) * SPITCH + q] = t.x;
        Qs[(d0 + 1) * SPITCH + q] = t.y;
        Qs[(d0 + 2) * SPITCH + q] = t.z;
        Qs[(d0 + 3) * SPITCH + q] = t.w;
    }

    float o_acc[4][4] = {};
    float m_r[4], l_r[4];
#pragma unroll
    for (int i = 0; i < 4; i++) { m_r[i] = -1e30f; l_r[i] = 0.0f; }

    const float scale = 0.125f;   // 1/sqrt(64)
    const int n_tiles = S / BK;

    for (int t = 0; t < n_tiles; t++) {
        const int k0 = t * BK;

        __syncthreads();   // previous GEMM2 done reading Vs/Ps

        // ---- load K (transposed) and V (natural) tiles ----
#pragma unroll
        for (int r = 0; r < 4; r++) {
            int v  = tid + r * NTHREADS;
            int k  = v >> 4;
            int d0 = (v & 15) << 2;
            float4 tk = *reinterpret_cast<const float4*>(Kb + (size_t)(k0 + k) * DH + d0);
            Ks[(d0 + 0) * SPITCH + k] = tk.x;
            Ks[(d0 + 1) * SPITCH + k] = tk.y;
            Ks[(d0 + 2) * SPITCH + k] = tk.z;
            Ks[(d0 + 3) * SPITCH + k] = tk.w;
            float4 tv = *reinterpret_cast<const float4*>(Vb + (size_t)(k0 + k) * DH + d0);
            *reinterpret_cast<float4*>(&Vs[k * SPITCH + d0]) = tv;
        }
        __syncthreads();

        // ---- GEMM1: S = Q @ K^T  (4x4 microtile per thread) ----
        float s[4][4] = {};
#pragma unroll 8
        for (int kk = 0; kk < DH; kk++) {
            float4 a4 = *reinterpret_cast<const float4*>(&Qs[kk * SPITCH + ty * 4]);
            float4 b4 = *reinterpret_cast<const float4*>(&Ks[kk * SPITCH + tx * 4]);
            float av[4] = {a4.x, a4.y, a4.z, a4.w};
            float bv[4] = {b4.x, b4.y, b4.z, b4.w};
#pragma unroll
            for (int i = 0; i < 4; i++)
#pragma unroll
                for (int j = 0; j < 4; j++)
                    s[i][j] += av[i] * bv[j];
        }

        // ---- mask + scale + online softmax (row groups of 16 lanes) ----
#pragma unroll
        for (int i = 0; i < 4; i++) {
            const int q = ty * 4 + i;
            const int4 mm = *reinterpret_cast<const int4*>(
                Mb + (size_t)q * S + k0 + tx * 4);
            s[i][0] = mm.x ? s[i][0] * scale : -1e20f;
            s[i][1] = mm.y ? s[i][1] * scale : -1e20f;
            s[i][2] = mm.z ? s[i][2] * scale : -1e20f;
            s[i][3] = mm.w ? s[i][3] * scale : -1e20f;

            float mt = fmaxf(fmaxf(s[i][0], s[i][1]), fmaxf(s[i][2], s[i][3]));
#pragma unroll
            for (int off = 8; off > 0; off >>= 1)
                mt = fmaxf(mt, __shfl_xor_sync(0xffffffffu, mt, off));

            float mn   = fmaxf(m_r[i], mt);
            float corr = __expf(m_r[i] - mn);
            m_r[i] = mn;

            float rs = 0.0f;
#pragma unroll
            for (int j = 0; j < 4; j++) {
                s[i][j] = __expf(s[i][j] - mn);
                rs += s[i][j];
            }
#pragma unroll
            for (int off = 8; off > 0; off >>= 1)
                rs += __shfl_xor_sync(0xffffffffu, rs, off);

            l_r[i] = l_r[i] * corr + rs;
#pragma unroll
            for (int j = 0; j < 4; j++) o_acc[i][j] *= corr;

            *reinterpret_cast<float4*>(&Ps[q * SPITCH + tx * 4]) =
                make_float4(s[i][0], s[i][1], s[i][2], s[i][3]);
        }
        __syncthreads();

        // ---- GEMM2: O += P @ V ----
#pragma unroll 8
        for (int kk = 0; kk < BK; kk++) {
            float4 v4 = *reinterpret_cast<const float4*>(&Vs[kk * SPITCH + tx * 4]);
            float vv[4] = {v4.x, v4.y, v4.z, v4.w};
            float pv[4];
#pragma unroll
            for (int i = 0; i < 4; i++)
                pv[i] = Ps[(ty * 4 + i) * SPITCH + kk];
#pragma unroll
            for (int i = 0; i < 4; i++)
#pragma unroll
                for (int j = 0; j < 4; j++)
                    o_acc[i][j] += pv[i] * vv[j];
        }
    }

    // ---- epilogue: normalize and store ----
    float* Ob = O + (((size_t)b * Hn + h) * S + q0) * DH;
#pragma unroll
    for (int i = 0; i < 4; i++) {
        float inv_l = 1.0f / l_r[i];
        float4 r = make_float4(o_acc[i][0] * inv_l, o_acc[i][1] * inv_l,
                               o_acc[i][2] * inv_l, o_acc[i][3] * inv_l);
        *reinterpret_cast<float4*>(Ob + (size_t)(ty * 4 + i) * DH + tx * 4) = r;
    }
}

extern "C" void kernel_launch(void* const* d_in, const int* in_sizes, int n_in,
                              void* d_out, int out_size)
{
    const float* Q    = (const float*)d_in[0];
    const float* K    = (const float*)d_in[1];
    const float* V    = (const float*)d_in[2];
    const int*   mask = (const int*)d_in[3];
    float*       O    = (float*)d_out;

    const int B = 2, H = 12, S = 2048;

    const int smem_bytes = (2 * DH * SPITCH + BK * SPITCH + BQ * SPITCH) * (int)sizeof(float);
    cudaFuncSetAttribute(attn_fp32_kernel,
                         cudaFuncAttributeMaxDynamicSharedMemorySize, smem_bytes);

    dim3 grid(S / BQ, H, B);
    dim3 block(NTHREADS);
    attn_fp32_kernel<<<grid, block, smem_bytes>>>(Q, K, V, mask, O, H, S);
}

// round 3
// speedup vs baseline: 2.5742x; 2.5742x over previous
#include <cuda_runtime.h>
#include <cuda_bf16.h>
#include <cstdint>

// Masked attention B=2 H=12 S=2048 D=64 fp32.
// FlashAttention-2 on tensor cores via mma.sync.m16n8k16 (bf16, row.col),
// hi/lo bf16 split (3 MMAs per GEMM) for ~fp32 accuracy.
// P stays in registers (MMA1 D-fragment == MMA2 A-fragment layout).
// 256 threads / 8 warps; warp w owns query rows [16w, 16w+16); BK=64.

#define HN 12
#define SLEN 2048
#define DH 64
#define BQ 128
#define BK 64
#define NTH 256
#define NTILES (SLEN / BK)
#define PW 36            // smem pitch in 32-bit words (= 72 bf16 = 144 B)

// dynamic smem word offsets
#define W_QH 0                       // 128 rows
#define W_QL (W_QH + 128 * PW)
#define W_KH (W_QL + 128 * PW)       // 64 rows
#define W_KL (W_KH + 64 * PW)
#define W_VH (W_KL + 64 * PW)       // Vt: 64 d-rows x 64 k-cols
#define W_VL (W_VH + 64 * PW)
#define SMEM_BYTES ((W_VL + 64 * PW) * 4)   // 73728

// pack two f32 -> bf16x2 (lo -> lower half / element0, hi -> upper half)
__device__ __forceinline__ uint32_t pack_bf(float lo, float hi) {
    uint32_t r;
    asm("cvt.rn.satfinite.bf16x2.f32 %0, %1, %2;" : "=r"(r) : "f"(hi), "f"(lo));
    return r;
}

__device__ __forceinline__ void mma_bf16(float* d,
                                         uint32_t a0, uint32_t a1, uint32_t a2, uint32_t a3,
                                         uint32_t b0, uint32_t b1) {
    asm volatile("mma.sync.aligned.m16n8k16.row.col.f32.bf16.bf16.f32 "
                 "{%0,%1,%2,%3},{%4,%5,%6,%7},{%8,%9},{%0,%1,%2,%3};"
                 : "+f"(d[0]), "+f"(d[1]), "+f"(d[2]), "+f"(d[3])
                 : "r"(a0), "r"(a1), "r"(a2), "r"(a3), "r"(b0), "r"(b1));
}

// split float4 pair into hi/lo bf16x2 words and store 8B to each plane
__device__ __forceinline__ void split_store(uint32_t* WH, uint32_t* WL,
                                            int widx, float4 v) {
    uint32_t h0 = pack_bf(v.x, v.y);
    uint32_t h1 = pack_bf(v.z, v.w);
    float hx = __uint_as_float(h0 << 16), hy = __uint_as_float(h0 & 0xffff0000u);
    float hz = __uint_as_float(h1 << 16), hw = __uint_as_float(h1 & 0xffff0000u);
    uint32_t l0 = pack_bf(v.x - hx, v.y - hy);
    uint32_t l1 = pack_bf(v.z - hz, v.w - hw);
    *reinterpret_cast<uint2*>(WH + widx) = make_uint2(h0, h1);
    *reinterpret_cast<uint2*>(WL + widx) = make_uint2(l0, l1);
}

__global__ void __launch_bounds__(NTH, 2)
attn_mma_kernel(const float* __restrict__ Q, const float* __restrict__ K,
                const float* __restrict__ V, const int* __restrict__ M,
                float* __restrict__ O)
{
    extern __shared__ uint32_t smw[];
    uint32_t* QH = smw + W_QH;  uint32_t* QL = smw + W_QL;
    uint32_t* KH = smw + W_KH;  uint32_t* KL = smw + W_KL;
    uint32_t* VH = smw + W_VH;  uint32_t* VL = smw + W_VL;

    const int tid  = threadIdx.x;
    const int lane = tid & 31;
    const int w    = tid >> 5;          // warp id 0..7
    const int g    = lane >> 2;         // row group 0..7
    const int qd   = lane & 3;          // quad lane 0..3

    const int b  = blockIdx.z, h = blockIdx.y;
    const int q0 = blockIdx.x * BQ;
    const size_t bh = (size_t)b * HN + h;
    const float* Qb = Q + (bh * SLEN + q0) * DH;
    const float* Kb = K + bh * SLEN * DH;
    const float* Vb = V + bh * SLEN * DH;
    const int*   Mb = M + (size_t)b * SLEN * SLEN;

    // ---- prologue: Q -> smem hi/lo ----
    {
        const int row = tid >> 1, c0 = (tid & 1) * 32;
        const float* src = Qb + (size_t)row * DH + c0;
#pragma unroll
        for (int i = 0; i < 8; i++) {
            float4 v = *reinterpret_cast<const float4*>(src + 4 * i);
            split_store(QH, QL, row * PW + ((c0 + 4 * i) >> 1), v);
        }
    }

    float s[8][4];
    float o[8][4] = {};
    float m0 = -1e30f, m1 = -1e30f, l0 = 0.0f, l1 = 0.0f;

    const int qrow = q0 + 16 * w + g;
    const int2* mp0 = reinterpret_cast<const int2*>(Mb + (size_t)qrow * SLEN);
    const int2* mp1 = reinterpret_cast<const int2*>(Mb + (size_t)(qrow + 8) * SLEN);

#pragma unroll 1
    for (int t = 0; t < NTILES; t++) {
        const int k0 = t * BK;

        __syncthreads();   // prior iteration done reading K/V smem

        // ---- K tile -> smem hi/lo (row-major [k][d]) ----
        {
            const int row = tid >> 2, c0 = (tid & 3) * 16;
            const float* src = Kb + (size_t)(k0 + row) * DH + c0;
#pragma unroll
            for (int i = 0; i < 4; i++) {
                float4 v = *reinterpret_cast<const float4*>(src + 4 * i);
                split_store(KH, KL, row * PW + ((c0 + 4 * i) >> 1), v);
            }
        }
        // ---- V tile -> smem transposed hi/lo (Vt[d][k]) ----
        {
            const int kk = (tid & 31) * 2, d0 = (tid >> 5) * 8;
            const float* r0 = Vb + (size_t)(k0 + kk) * DH + d0;
            const float* r1 = r0 + DH;
            float4 a0v = *reinterpret_cast<const float4*>(r0);
            float4 a1v = *reinterpret_cast<const float4*>(r0 + 4);
            float4 b0v = *reinterpret_cast<const float4*>(r1);
            float4 b1v = *reinterpret_cast<const float4*>(r1 + 4);
            const float* ap = &a0v.x;
            const float* bp = &b0v.x;
#pragma unroll
            for (int dd = 0; dd < 8; dd++) {
                float va = (dd < 4) ? ap[dd] : (&a1v.x)[dd - 4];
                float vb = (dd < 4) ? bp[dd] : (&b1v.x)[dd - 4];
                uint32_t hw = pack_bf(va, vb);
                float ha = __uint_as_float(hw << 16);
                float hb = __uint_as_float(hw & 0xffff0000u);
                uint32_t lw = pack_bf(va - ha, vb - hb);
                const int widx = (d0 + dd) * PW + (kk >> 1);
                VH[widx] = hw;
                VL[widx] = lw;
            }
        }
        __syncthreads();

        // ---- MMA1: S = Qh*Kh + Qh*Kl + Ql*Kh ----
#pragma unroll
        for (int j = 0; j < 8; j++) { s[j][0] = s[j][1] = s[j][2] = s[j][3] = 0.0f; }
#pragma unroll
        for (int kc = 0; kc < 4; kc++) {
            const int ab = (16 * w + g) * PW + 8 * kc + qd;
            uint32_t qh0 = QH[ab],           qh1 = QH[ab + 8 * PW];
            uint32_t qh2 = QH[ab + 4],       qh3 = QH[ab + 8 * PW + 4];
            uint32_t ql0 = QL[ab],           ql1 = QL[ab + 8 * PW];
            uint32_t ql2 = QL[ab + 4],       ql3 = QL[ab + 8 * PW + 4];
#pragma unroll
            for (int j = 0; j < 8; j++) {
                const int bb = (8 * j + g) * PW + 8 * kc + qd;
                uint32_t bh0 = KH[bb], bh1 = KH[bb + 4];
                uint32_t bl0 = KL[bb], bl1 = KL[bb + 4];
                mma_bf16(s[j], qh0, qh1, qh2, qh3, bh0, bh1);
                mma_bf16(s[j], qh0, qh1, qh2, qh3, bl0, bl1);
                mma_bf16(s[j], ql0, ql1, ql2, ql3, bh0, bh1);
            }
        }

        // ---- mask + scale + online softmax (registers only) ----
        float mt0 = -1e30f, mt1 = -1e30f;
#pragma unroll
        for (int j = 0; j < 8; j++) {
            const int ci = (k0 + 8 * j) >> 1;   // int2 index at col k0+8j
            int2 ma = mp0[ci + qd];
            int2 mb2 = mp1[ci + qd];
            s[j][0] = ma.x  ? s[j][0] * 0.125f : -1e20f;
            s[j][1] = ma.y  ? s[j][1] * 0.125f : -1e20f;
            s[j][2] = mb2.x ? s[j][2] * 0.125f : -1e20f;
            s[j][3] = mb2.y ? s[j][3] * 0.125f : -1e20f;
            mt0 = fmaxf(mt0, fmaxf(s[j][0], s[j][1]));
            mt1 = fmaxf(mt1, fmaxf(s[j][2], s[j][3]));
        }
        mt0 = fmaxf(mt0, __shfl_xor_sync(0xffffffffu, mt0, 1));
        mt0 = fmaxf(mt0, __shfl_xor_sync(0xffffffffu, mt0, 2));
        mt1 = fmaxf(mt1, __shfl_xor_sync(0xffffffffu, mt1, 1));
        mt1 = fmaxf(mt1, __shfl_xor_sync(0xffffffffu, mt1, 2));

        const float mn0 = fmaxf(m0, mt0), mn1 = fmaxf(m1, mt1);
        const float c0f = __expf(m0 - mn0), c1f = __expf(m1 - mn1);
        m0 = mn0; m1 = mn1;

        float rs0 = 0.0f, rs1 = 0.0f;
#pragma unroll
        for (int j = 0; j < 8; j++) {
            s[j][0] = __expf(s[j][0] - mn0);
            s[j][1] = __expf(s[j][1] - mn0);
            s[j][2] = __expf(s[j][2] - mn1);
            s[j][3] = __expf(s[j][3] - mn1);
            rs0 += s[j][0] + s[j][1];
            rs1 += s[j][2] + s[j][3];
        }
        rs0 += __shfl_xor_sync(0xffffffffu, rs0, 1);
        rs0 += __shfl_xor_sync(0xffffffffu, rs0, 2);
        rs1 += __shfl_xor_sync(0xffffffffu, rs1, 1);
        rs1 += __shfl_xor_sync(0xffffffffu, rs1, 2);
        l0 = l0 * c0f + rs0;
        l1 = l1 * c1f + rs1;

#pragma unroll
        for (int j = 0; j < 8; j++) {
            o[j][0] *= c0f; o[j][1] *= c0f;
            o[j][2] *= c1f; o[j][3] *= c1f;
        }

        // ---- MMA2: O += Ph*Vh + Ph*Vl + Pl*Vh  (P from registers) ----
#pragma unroll
        for (int kc = 0; kc < 4; kc++) {
            uint32_t ph0 = pack_bf(s[2 * kc][0], s[2 * kc][1]);
            uint32_t ph1 = pack_bf(s[2 * kc][2], s[2 * kc][3]);
            uint32_t ph2 = pack_bf(s[2 * kc + 1][0], s[2 * kc + 1][1]);
            uint32_t ph3 = pack_bf(s[2 * kc + 1][2], s[2 * kc + 1][3]);
            uint32_t pl0, pl1, pl2, pl3;
            {
                float a = __uint_as_float(ph0 << 16), bq = __uint_as_float(ph0 & 0xffff0000u);
                pl0 = pack_bf(s[2 * kc][0] - a, s[2 * kc][1] - bq);
                a = __uint_as_float(ph1 << 16); bq = __uint_as_float(ph1 & 0xffff0000u);
                pl1 = pack_bf(s[2 * kc][2] - a, s[2 * kc][3] - bq);
                a = __uint_as_float(ph2 << 16); bq = __uint_as_float(ph2 & 0xffff0000u);
                pl2 = pack_bf(s[2 * kc + 1][0] - a, s[2 * kc + 1][1] - bq);
                a = __uint_as_float(ph3 << 16); bq = __uint_as_float(ph3 & 0xffff0000u);
                pl3 = pack_bf(s[2 * kc + 1][2] - a, s[2 * kc + 1][3] - bq);
            }
#pragma unroll
            for (int j = 0; j < 8; j++) {
                const int bb = (8 * j + g) * PW + 8 * kc + qd;
                uint32_t bh0 = VH[bb], bh1 = VH[bb + 4];
                uint32_t bl0 = VL[bb], bl1 = VL[bb + 4];
                mma_bf16(o[j], ph0, ph1, ph2, ph3, bh0, bh1);
                mma_bf16(o[j], ph0, ph1, ph2, ph3, bl0, bl1);
                mma_bf16(o[j], pl0, pl1, pl2, pl3, bh0, bh1);
            }
        }
    }

    // ---- epilogue ----
    const float i0 = 1.0f / l0, i1 = 1.0f / l1;
    float* Ob0 = O + (bh * SLEN + qrow) * DH;
    float* Ob1 = Ob0 + 8 * DH;
#pragma unroll
    for (int j = 0; j < 8; j++) {
        const int cc = 8 * j + qd * 2;
        *reinterpret_cast<float2*>(Ob0 + cc) = make_float2(o[j][0] * i0, o[j][1] * i0);
        *reinterpret_cast<float2*>(Ob1 + cc) = make_float2(o[j][2] * i1, o[j][3] * i1);
    }
}

extern "C" void kernel_launch(void* const* d_in, const int* in_sizes, int n_in,
                              void* d_out, int out_size)
{
    const float* Q    = (const float*)d_in[0];
    const float* K    = (const float*)d_in[1];
    const float* V    = (const float*)d_in[2];
    const int*   mask = (const int*)d_in[3];
    float*       O    = (float*)d_out;

    cudaFuncSetAttribute(attn_mma_kernel,
                         cudaFuncAttributeMaxDynamicSharedMemorySize, SMEM_BYTES);

    dim3 grid(SLEN / BQ, HN, 2);   // 16 x 12 x 2 = 384 CTAs
    attn_mma_kernel<<<grid, NTH, SMEM_BYTES>>>(Q, K, V, mask, O);
}